// round 1
// baseline (speedup 1.0000x reference)
#include <cuda_runtime.h>
#include <math.h>
#include <stdint.h>

#define NB    8
#define NC    256
#define HID   512
#define NPIX  4096
#define NHEAD 8
#define DHEAD 64

// ---------------- scratch (static device globals; no allocation) ----------------
__device__ __align__(256) float g_q[NB * HID * NPIX];      // 67 MB
__device__ __align__(256) float g_k[NB * HID * NPIX];      // 67 MB
__device__ __align__(256) float g_v[NB * HID * NPIX];      // 67 MB
__device__ __align__(256) float g_rmax[NB * HID];
__device__ __align__(256) float g_rinv[NB * HID];
__device__ __align__(256) float g_ctx[NB * NHEAD * DHEAD * DHEAD];  // 1 MB
__device__ __align__(256) float g_fold[NB * NC * HID];              // 4 MB

// ---------------- generic batched SGEMM: C = alpha * A@B (+bias) ----------------
// A: M x K row-major (per-batch stride sA; 0 => shared weight)
// B: K x N row-major (per-batch stride sB)
// C: M x N row-major (per-batch stride sC)
// BM=BN=64, BK=16, 256 threads, 4x4 per thread.
__global__ void sgemm64_kernel(const float* __restrict__ A, long sA,
                               const float* __restrict__ B, long sB,
                               float* __restrict__ C, long sC,
                               const float* __restrict__ bias,
                               int M, int N, int K, float alpha)
{
    const int bb = blockIdx.z;
    A += (size_t)bb * sA;
    B += (size_t)bb * sB;
    C += (size_t)bb * sC;

    __shared__ float As[16][64];
    __shared__ float Bs[16][64];

    const int tid = threadIdx.x;
    const int tx = tid & 15, ty = tid >> 4;
    const int m0 = blockIdx.y * 64, n0 = blockIdx.x * 64;

    // A-load coords: 64 rows x 16 k, float4 along K
    const int arow = tid >> 2;
    const int akq  = (tid & 3) << 2;
    // B-load coords: 16 k x 64 n, float4 along N
    const int bkb = tid >> 4;
    const int bn4 = (tid & 15) << 2;

    float acc[4][4] = {};

    for (int k0 = 0; k0 < K; k0 += 16) {
        float4 a = *(const float4*)(A + (size_t)(m0 + arow) * K + k0 + akq);
        As[akq + 0][arow] = a.x;
        As[akq + 1][arow] = a.y;
        As[akq + 2][arow] = a.z;
        As[akq + 3][arow] = a.w;

        float4 bv = *(const float4*)(B + (size_t)(k0 + bkb) * N + n0 + bn4);
        *(float4*)&Bs[bkb][bn4] = bv;

        __syncthreads();

        #pragma unroll
        for (int kk = 0; kk < 16; kk++) {
            float ar[4], br[4];
            #pragma unroll
            for (int i = 0; i < 4; i++) ar[i] = As[kk][ty * 4 + i];
            #pragma unroll
            for (int j = 0; j < 4; j++) br[j] = Bs[kk][tx * 4 + j];
            #pragma unroll
            for (int i = 0; i < 4; i++)
                #pragma unroll
                for (int j = 0; j < 4; j++)
                    acc[i][j] += ar[i] * br[j];
        }
        __syncthreads();
    }

    #pragma unroll
    for (int i = 0; i < 4; i++) {
        const int m = m0 + ty * 4 + i;
        const float bi = bias ? bias[m] : 0.0f;
        float4 o4;
        o4.x = acc[i][0] * alpha + bi;
        o4.y = acc[i][1] * alpha + bi;
        o4.z = acc[i][2] * alpha + bi;
        o4.w = acc[i][3] * alpha + bi;
        *(float4*)(C + (size_t)m * N + n0 + tx * 4) = o4;
    }
}

// ---------------- per-row softmax stats over m (length 4096) ----------------
// One block per row (NB*HID rows), 256 threads, 16 elems/thread.
__global__ void softmax_stats_kernel(const float* __restrict__ Km,
                                     float* __restrict__ rmax,
                                     float* __restrict__ rinv)
{
    const int row = blockIdx.x;
    const float* p = Km + (size_t)row * NPIX;
    const int tid = threadIdx.x;

    float v[16];
    float m = -1e30f;
    #pragma unroll
    for (int i = 0; i < 16; i++) {
        v[i] = p[tid + (i << 8)];
        m = fmaxf(m, v[i]);
    }

    __shared__ float red[8];
    #pragma unroll
    for (int o = 16; o > 0; o >>= 1) m = fmaxf(m, __shfl_xor_sync(0xffffffffu, m, o));
    if ((tid & 31) == 0) red[tid >> 5] = m;
    __syncthreads();
    if (tid < 32) {
        float t = (tid < 8) ? red[tid] : -1e30f;
        #pragma unroll
        for (int o = 4; o > 0; o >>= 1) t = fmaxf(t, __shfl_xor_sync(0xffffffffu, t, o));
        if (tid == 0) red[0] = t;
    }
    __syncthreads();
    m = red[0];
    __syncthreads();

    float s = 0.0f;
    #pragma unroll
    for (int i = 0; i < 16; i++) s += expf(v[i] - m);
    #pragma unroll
    for (int o = 16; o > 0; o >>= 1) s += __shfl_xor_sync(0xffffffffu, s, o);
    if ((tid & 31) == 0) red[tid >> 5] = s;
    __syncthreads();
    if (tid == 0) {
        float t = 0.0f;
        #pragma unroll
        for (int i = 0; i < 8; i++) t += red[i];
        rmax[row] = m;
        rinv[row] = 1.0f / t;
    }
}

// ---------------- ctx[d][e] = sum_m softmax(k)[d,m] * v[e,m], per (b,h) ----------------
// NT GEMM 64x64xK=4096 with exp applied at A-tile load. One block per (b,h).
__global__ void ctx_kernel(const float* __restrict__ Km, const float* __restrict__ Vm,
                           const float* __restrict__ rmax, const float* __restrict__ rinv,
                           float* __restrict__ ctx)
{
    const int bh = blockIdx.x;  // b*8 + h
    const float* kp = Km + (size_t)bh * 64 * NPIX;
    const float* vp = Vm + (size_t)bh * 64 * NPIX;

    __shared__ float As[32][65];
    __shared__ float Bs[32][65];

    const int tid = threadIdx.x;
    const int tx = tid & 15, ty = tid >> 4;
    const int d  = tid >> 2;        // 0..63 (row this thread loads)
    const int m8 = (tid & 3) << 3;  // 0,8,16,24

    const float myMax = rmax[bh * 64 + d];
    const float myInv = rinv[bh * 64 + d];

    float acc[4][4] = {};

    for (int m0 = 0; m0 < NPIX; m0 += 32) {
        const float* krow = kp + (size_t)d * NPIX + m0 + m8;
        const float* vrow = vp + (size_t)d * NPIX + m0 + m8;
        float4 a0 = *(const float4*)(krow);
        float4 a1 = *(const float4*)(krow + 4);
        As[m8 + 0][d] = expf(a0.x - myMax) * myInv;
        As[m8 + 1][d] = expf(a0.y - myMax) * myInv;
        As[m8 + 2][d] = expf(a0.z - myMax) * myInv;
        As[m8 + 3][d] = expf(a0.w - myMax) * myInv;
        As[m8 + 4][d] = expf(a1.x - myMax) * myInv;
        As[m8 + 5][d] = expf(a1.y - myMax) * myInv;
        As[m8 + 6][d] = expf(a1.z - myMax) * myInv;
        As[m8 + 7][d] = expf(a1.w - myMax) * myInv;
        float4 b0 = *(const float4*)(vrow);
        float4 b1 = *(const float4*)(vrow + 4);
        Bs[m8 + 0][d] = b0.x; Bs[m8 + 1][d] = b0.y;
        Bs[m8 + 2][d] = b0.z; Bs[m8 + 3][d] = b0.w;
        Bs[m8 + 4][d] = b1.x; Bs[m8 + 5][d] = b1.y;
        Bs[m8 + 6][d] = b1.z; Bs[m8 + 7][d] = b1.w;

        __syncthreads();

        #pragma unroll
        for (int kk = 0; kk < 32; kk++) {
            float ar[4], br[4];
            #pragma unroll
            for (int i = 0; i < 4; i++) ar[i] = As[kk][ty * 4 + i];
            #pragma unroll
            for (int j = 0; j < 4; j++) br[j] = Bs[kk][tx * 4 + j];
            #pragma unroll
            for (int i = 0; i < 4; i++)
                #pragma unroll
                for (int j = 0; j < 4; j++)
                    acc[i][j] += ar[i] * br[j];
        }
        __syncthreads();
    }

    float* cp = ctx + (size_t)bh * 4096;
    #pragma unroll
    for (int i = 0; i < 4; i++)
        #pragma unroll
        for (int j = 0; j < 4; j++)
            cp[(ty * 4 + i) * 64 + tx * 4 + j] = acc[i][j];
}

// ---------------- fold[b][o][h*64+d] = sum_e Wo[o][h*64+e] * ctx[b][h][d][e] ----------------
__global__ void fold_kernel(const float* __restrict__ Wo, const float* __restrict__ ctx,
                            float* __restrict__ fold)
{
    const int bh = blockIdx.x;
    const int b = bh >> 3, h = bh & 7;

    __shared__ float cs[64][64];
    const float* cp = ctx + (size_t)bh * 4096;
    for (int i = threadIdx.x; i < 4096; i += 256)
        cs[i >> 6][i & 63] = cp[i];
    __syncthreads();

    const int o = threadIdx.x;  // 0..255
    float w[64];
    #pragma unroll
    for (int e = 0; e < 64; e++) w[e] = Wo[(size_t)o * HID + h * 64 + e];

    float* fp = fold + ((size_t)b * NC + o) * HID + h * 64;
    for (int dd = 0; dd < 64; dd++) {
        float s = 0.0f;
        #pragma unroll
        for (int e = 0; e < 64; e++) s += w[e] * cs[dd][e];
        fp[dd] = s;
    }
}

// ---------------- launch ----------------
extern "C" void kernel_launch(void* const* d_in, const int* in_sizes, int n_in,
                              void* d_out, int out_size)
{
    const float* x    = (const float*)d_in[0];
    const float* cin  = (const float*)d_in[1];
    const float* Wq   = (const float*)d_in[2];
    const float* Wk   = (const float*)d_in[3];
    const float* Wv   = (const float*)d_in[4];
    const float* Wo   = (const float*)d_in[5];
    const float* bo   = (const float*)d_in[6];
    float* out = (float*)d_out;

    float *qp, *kp, *vp, *rm, *ri, *cx, *fd;
    cudaGetSymbolAddress((void**)&qp, g_q);
    cudaGetSymbolAddress((void**)&kp, g_k);
    cudaGetSymbolAddress((void**)&vp, g_v);
    cudaGetSymbolAddress((void**)&rm, g_rmax);
    cudaGetSymbolAddress((void**)&ri, g_rinv);
    cudaGetSymbolAddress((void**)&cx, g_ctx);
    cudaGetSymbolAddress((void**)&fd, g_fold);

    const float scale = 0.125f;  // 64^-0.5

    // projections: q = scale * Wq@x, k = Wk@ctx, v = Wv@ctx   (per batch)
    dim3 gproj(NPIX / 64, HID / 64, NB);
    sgemm64_kernel<<<gproj, 256>>>(Wq, 0, x,   (long)NC * NPIX, qp, (long)HID * NPIX,
                                   nullptr, HID, NPIX, NC, scale);
    sgemm64_kernel<<<gproj, 256>>>(Wk, 0, cin, (long)NC * NPIX, kp, (long)HID * NPIX,
                                   nullptr, HID, NPIX, NC, 1.0f);
    sgemm64_kernel<<<gproj, 256>>>(Wv, 0, cin, (long)NC * NPIX, vp, (long)HID * NPIX,
                                   nullptr, HID, NPIX, NC, 1.0f);

    // softmax stats over m for each k row
    softmax_stats_kernel<<<NB * HID, 256>>>(kp, rm, ri);

    // ctx = softmax(k) @ v^T per (b,h)
    ctx_kernel<<<NB * NHEAD, 256>>>(kp, vp, rm, ri, cx);

    // fold Wo into ctx
    fold_kernel<<<NB * NHEAD, 256>>>(Wo, cx, fd);

    // y = fold @ q + bo   (per batch)
    dim3 gfin(NPIX / 64, NC / 64, NB);
    sgemm64_kernel<<<gfin, 256>>>(fd, (long)NC * HID, qp, (long)HID * NPIX,
                                  out, (long)NC * NPIX, bo, NC, NPIX, HID, 1.0f);
}

// round 2
// speedup vs baseline: 1.8249x; 1.8249x over previous
#include <cuda_runtime.h>
#include <math.h>
#include <stdint.h>

#define NB    8
#define NC    256
#define HID   512
#define NPIX  4096
#define NHEAD 8
#define DHEAD 64
#define NCHUNK 16

typedef unsigned long long ull;

// ---------------- scratch (static device globals; no allocation) ----------------
__device__ __align__(256) float g_k[NB * HID * NPIX];      // 67 MB
__device__ __align__(256) float g_v[NB * HID * NPIX];      // 67 MB
__device__ __align__(256) float g_rmax[NB * HID];
__device__ __align__(256) float g_rinv[NB * HID];
__device__ __align__(256) float g_part[NCHUNK * NB * NHEAD * DHEAD * DHEAD]; // 16.7 MB
__device__ __align__(256) float g_fold[NB * NC * HID];              // 4 MB
__device__ __align__(256) float g_comb[NB * NC * NC];               // 2 MB

__device__ __forceinline__ void ffma2(ull& d, ull a, ull b) {
    asm("fma.rn.f32x2 %0, %1, %2, %0;" : "+l"(d) : "l"(a), "l"(b));
}

// ---------------- 128x128 SGEMM with packed f32x2 FMA ----------------
// C = alpha * A@B (+bias[m]).  A: MxK rm (batch stride sA, 0=shared),
// B: KxN rm (stride sB), C: MxN rm (stride sC). BM=BN=128, BK=16, 256 thr, 8x8/thread.
__global__ __launch_bounds__(256, 2)
void sgemm128_kernel(const float* __restrict__ A, long sA,
                     const float* __restrict__ B, long sB,
                     float* __restrict__ C, long sC,
                     const float* __restrict__ bias,
                     int M, int N, int K, float alpha)
{
    const int bb = blockIdx.z;
    A += (size_t)bb * sA;
    B += (size_t)bb * sB;
    C += (size_t)bb * sC;

    // As holds A transposed AND duplicated: As[k][2*m+0] = As[k][2*m+1] = A[m][k]
    __shared__ float As[16][256];
    __shared__ float Bs[16][128];

    const int tid = threadIdx.x;
    const int tx = tid & 15, ty = tid >> 4;
    const int m0 = blockIdx.y * 128, n0 = blockIdx.x * 128;

    const int arow = tid >> 2;       // 0..63
    const int akq  = (tid & 3) << 2; // 0,4,8,12
    const int bk   = tid >> 4;       // 0..15
    const int bn   = (tid & 15) << 2;

    ull acc[8][4];
    #pragma unroll
    for (int i = 0; i < 8; i++)
        #pragma unroll
        for (int j = 0; j < 4; j++) acc[i][j] = 0ull;

    for (int k0 = 0; k0 < K; k0 += 16) {
        #pragma unroll
        for (int r = 0; r < 2; r++) {
            const int mr = arow + r * 64;
            float4 a = *(const float4*)(A + (size_t)(m0 + mr) * K + k0 + akq);
            *(float2*)&As[akq + 0][2 * mr] = make_float2(a.x, a.x);
            *(float2*)&As[akq + 1][2 * mr] = make_float2(a.y, a.y);
            *(float2*)&As[akq + 2][2 * mr] = make_float2(a.z, a.z);
            *(float2*)&As[akq + 3][2 * mr] = make_float2(a.w, a.w);
        }
        #pragma unroll
        for (int p = 0; p < 2; p++) {
            *(float4*)&Bs[bk][bn + p * 64] =
                *(const float4*)(B + (size_t)(k0 + bk) * N + n0 + bn + p * 64);
        }
        __syncthreads();

        #pragma unroll
        for (int kk = 0; kk < 16; kk++) {
            ulonglong2 aA = *(ulonglong2*)&As[kk][8 * ty];
            ulonglong2 aB = *(ulonglong2*)&As[kk][8 * ty + 4];
            ulonglong2 aC = *(ulonglong2*)&As[kk][128 + 8 * ty];
            ulonglong2 aD = *(ulonglong2*)&As[kk][128 + 8 * ty + 4];
            ulonglong2 bA = *(ulonglong2*)&Bs[kk][4 * tx];
            ulonglong2 bB = *(ulonglong2*)&Bs[kk][4 * tx + 64];
            ull a2[8] = {aA.x, aA.y, aB.x, aB.y, aC.x, aC.y, aD.x, aD.y};
            ull b2[4] = {bA.x, bA.y, bB.x, bB.y};
            #pragma unroll
            for (int i = 0; i < 8; i++)
                #pragma unroll
                for (int j = 0; j < 4; j++)
                    ffma2(acc[i][j], a2[i], b2[j]);
        }
        __syncthreads();
    }

    #pragma unroll
    for (int i = 0; i < 8; i++) {
        const int m = m0 + ((i < 4) ? (ty * 4 + i) : (64 + ty * 4 + i - 4));
        const float bi = bias ? bias[m] : 0.0f;
        float2 f0 = *(float2*)&acc[i][0];
        float2 f1 = *(float2*)&acc[i][1];
        float2 f2 = *(float2*)&acc[i][2];
        float2 f3 = *(float2*)&acc[i][3];
        float4 o0 = make_float4(f0.x * alpha + bi, f0.y * alpha + bi,
                                f1.x * alpha + bi, f1.y * alpha + bi);
        float4 o1 = make_float4(f2.x * alpha + bi, f2.y * alpha + bi,
                                f3.x * alpha + bi, f3.y * alpha + bi);
        *(float4*)(C + (size_t)m * N + n0 + tx * 4) = o0;
        *(float4*)(C + (size_t)m * N + n0 + 64 + tx * 4) = o1;
    }
}

// ---------------- 64x64 SGEMM (for the small combine GEMM) ----------------
__global__ void sgemm64_kernel(const float* __restrict__ A, long sA,
                               const float* __restrict__ B, long sB,
                               float* __restrict__ C, long sC,
                               const float* __restrict__ bias,
                               int M, int N, int K, float alpha)
{
    const int bb = blockIdx.z;
    A += (size_t)bb * sA;
    B += (size_t)bb * sB;
    C += (size_t)bb * sC;

    __shared__ float As[16][64];
    __shared__ float Bs[16][64];

    const int tid = threadIdx.x;
    const int tx = tid & 15, ty = tid >> 4;
    const int m0 = blockIdx.y * 64, n0 = blockIdx.x * 64;
    const int arow = tid >> 2;
    const int akq  = (tid & 3) << 2;
    const int bkb = tid >> 4;
    const int bn4 = (tid & 15) << 2;

    float acc[4][4] = {};

    for (int k0 = 0; k0 < K; k0 += 16) {
        float4 a = *(const float4*)(A + (size_t)(m0 + arow) * K + k0 + akq);
        As[akq + 0][arow] = a.x;
        As[akq + 1][arow] = a.y;
        As[akq + 2][arow] = a.z;
        As[akq + 3][arow] = a.w;
        *(float4*)&Bs[bkb][bn4] = *(const float4*)(B + (size_t)(k0 + bkb) * N + n0 + bn4);
        __syncthreads();

        #pragma unroll
        for (int kk = 0; kk < 16; kk++) {
            float ar[4], br[4];
            #pragma unroll
            for (int i = 0; i < 4; i++) ar[i] = As[kk][ty * 4 + i];
            #pragma unroll
            for (int j = 0; j < 4; j++) br[j] = Bs[kk][tx * 4 + j];
            #pragma unroll
            for (int i = 0; i < 4; i++)
                #pragma unroll
                for (int j = 0; j < 4; j++)
                    acc[i][j] += ar[i] * br[j];
        }
        __syncthreads();
    }

    #pragma unroll
    for (int i = 0; i < 4; i++) {
        const int m = m0 + ty * 4 + i;
        const float bi = bias ? bias[m] : 0.0f;
        float4 o4;
        o4.x = acc[i][0] * alpha + bi;
        o4.y = acc[i][1] * alpha + bi;
        o4.z = acc[i][2] * alpha + bi;
        o4.w = acc[i][3] * alpha + bi;
        *(float4*)(C + (size_t)m * N + n0 + tx * 4) = o4;
    }
}

// ---------------- per-row softmax stats over m ----------------
__global__ void softmax_stats_kernel(const float* __restrict__ Km,
                                     float* __restrict__ rmax,
                                     float* __restrict__ rinv)
{
    const int row = blockIdx.x;
    const float* p = Km + (size_t)row * NPIX;
    const int tid = threadIdx.x;

    float v[16];
    float m = -1e30f;
    #pragma unroll
    for (int i = 0; i < 16; i++) {
        v[i] = p[tid + (i << 8)];
        m = fmaxf(m, v[i]);
    }

    __shared__ float red[8];
    #pragma unroll
    for (int o = 16; o > 0; o >>= 1) m = fmaxf(m, __shfl_xor_sync(0xffffffffu, m, o));
    if ((tid & 31) == 0) red[tid >> 5] = m;
    __syncthreads();
    if (tid < 32) {
        float t = (tid < 8) ? red[tid] : -1e30f;
        #pragma unroll
        for (int o = 4; o > 0; o >>= 1) t = fmaxf(t, __shfl_xor_sync(0xffffffffu, t, o));
        if (tid == 0) red[0] = t;
    }
    __syncthreads();
    m = red[0];
    __syncthreads();

    float s = 0.0f;
    #pragma unroll
    for (int i = 0; i < 16; i++) s += expf(v[i] - m);
    #pragma unroll
    for (int o = 16; o > 0; o >>= 1) s += __shfl_xor_sync(0xffffffffu, s, o);
    if ((tid & 31) == 0) red[tid >> 5] = s;
    __syncthreads();
    if (tid == 0) {
        float t = 0.0f;
        #pragma unroll
        for (int i = 0; i < 8; i++) t += red[i];
        rmax[row] = m;
        rinv[row] = 1.0f / t;
    }
}

// ---------------- ctx partial: split-K over m ----------------
// partial[ch][bh][d][e] = sum_{m in chunk} softmax(k)[d,m] * v[e,m]
__global__ void ctx_partial_kernel(const float* __restrict__ Km, const float* __restrict__ Vm,
                                   const float* __restrict__ rmax, const float* __restrict__ rinv,
                                   float* __restrict__ part)
{
    const int bh = blockIdx.x;
    const int ch = blockIdx.y;
    const float* kp = Km + (size_t)bh * 64 * NPIX;
    const float* vp = Vm + (size_t)bh * 64 * NPIX;

    __shared__ float As[32][65];
    __shared__ float Bs[32][65];

    const int tid = threadIdx.x;
    const int tx = tid & 15, ty = tid >> 4;
    const int d  = tid >> 2;
    const int m8 = (tid & 3) << 3;

    const float myMax = rmax[bh * 64 + d];
    const float myInv = rinv[bh * 64 + d];

    float acc[4][4] = {};
    const int mbeg = ch * (NPIX / NCHUNK);
    const int mend = mbeg + (NPIX / NCHUNK);

    for (int m0 = mbeg; m0 < mend; m0 += 32) {
        const float* krow = kp + (size_t)d * NPIX + m0 + m8;
        const float* vrow = vp + (size_t)d * NPIX + m0 + m8;
        float4 a0 = *(const float4*)(krow);
        float4 a1 = *(const float4*)(krow + 4);
        As[m8 + 0][d] = expf(a0.x - myMax) * myInv;
        As[m8 + 1][d] = expf(a0.y - myMax) * myInv;
        As[m8 + 2][d] = expf(a0.z - myMax) * myInv;
        As[m8 + 3][d] = expf(a0.w - myMax) * myInv;
        As[m8 + 4][d] = expf(a1.x - myMax) * myInv;
        As[m8 + 5][d] = expf(a1.y - myMax) * myInv;
        As[m8 + 6][d] = expf(a1.z - myMax) * myInv;
        As[m8 + 7][d] = expf(a1.w - myMax) * myInv;
        float4 b0 = *(const float4*)(vrow);
        float4 b1 = *(const float4*)(vrow + 4);
        Bs[m8 + 0][d] = b0.x; Bs[m8 + 1][d] = b0.y;
        Bs[m8 + 2][d] = b0.z; Bs[m8 + 3][d] = b0.w;
        Bs[m8 + 4][d] = b1.x; Bs[m8 + 5][d] = b1.y;
        Bs[m8 + 6][d] = b1.z; Bs[m8 + 7][d] = b1.w;

        __syncthreads();

        #pragma unroll
        for (int kk = 0; kk < 32; kk++) {
            float ar[4], br[4];
            #pragma unroll
            for (int i = 0; i < 4; i++) ar[i] = As[kk][ty * 4 + i];
            #pragma unroll
            for (int j = 0; j < 4; j++) br[j] = Bs[kk][tx * 4 + j];
            #pragma unroll
            for (int i = 0; i < 4; i++)
                #pragma unroll
                for (int j = 0; j < 4; j++)
                    acc[i][j] += ar[i] * br[j];
        }
        __syncthreads();
    }

    float* cp = part + ((size_t)ch * 64 + bh) * 4096;
    #pragma unroll
    for (int i = 0; i < 4; i++)
        #pragma unroll
        for (int j = 0; j < 4; j++)
            cp[(ty * 4 + i) * 64 + tx * 4 + j] = acc[i][j];
}

// ---------------- reduce partials + fold Wo ----------------
// fold[b][o][h*64+d] = sum_e Wo[o][h*64+e] * ctx[b][h][d][e]
__global__ void fold_kernel(const float* __restrict__ Wo, const float* __restrict__ part,
                            float* __restrict__ fold)
{
    const int bh = blockIdx.x;
    const int b = bh >> 3, h = bh & 7;

    __shared__ float cs[64][64];
    for (int i = threadIdx.x; i < 4096; i += 256) {
        float s = 0.0f;
        #pragma unroll
        for (int ch = 0; ch < NCHUNK; ch++)
            s += part[((size_t)ch * 64 + bh) * 4096 + i];
        cs[i >> 6][i & 63] = s;
    }
    __syncthreads();

    const int o = threadIdx.x;  // 0..255
    float w[64];
    #pragma unroll
    for (int e = 0; e < 64; e++) w[e] = Wo[(size_t)o * HID + h * 64 + e];

    float* fp = fold + ((size_t)b * NC + o) * HID + h * 64;
    for (int dd = 0; dd < 64; dd++) {
        float s = 0.0f;
        #pragma unroll
        for (int e = 0; e < 64; e++) s += w[e] * cs[dd][e];
        fp[dd] = s;
    }
}

// ---------------- launch ----------------
extern "C" void kernel_launch(void* const* d_in, const int* in_sizes, int n_in,
                              void* d_out, int out_size)
{
    const float* x    = (const float*)d_in[0];
    const float* cin  = (const float*)d_in[1];
    const float* Wq   = (const float*)d_in[2];
    const float* Wk   = (const float*)d_in[3];
    const float* Wv   = (const float*)d_in[4];
    const float* Wo   = (const float*)d_in[5];
    const float* bo   = (const float*)d_in[6];
    float* out = (float*)d_out;

    float *kp, *vp, *rm, *ri, *pt, *fd, *cb;
    cudaGetSymbolAddress((void**)&kp, g_k);
    cudaGetSymbolAddress((void**)&vp, g_v);
    cudaGetSymbolAddress((void**)&rm, g_rmax);
    cudaGetSymbolAddress((void**)&ri, g_rinv);
    cudaGetSymbolAddress((void**)&pt, g_part);
    cudaGetSymbolAddress((void**)&fd, g_fold);
    cudaGetSymbolAddress((void**)&cb, g_comb);

    const float scale = 0.125f;  // 64^-0.5

    // k = Wk@context, v = Wv@context (per batch)
    dim3 gproj(NPIX / 128, HID / 128, NB);
    sgemm128_kernel<<<gproj, 256>>>(Wk, 0, cin, (long)NC * NPIX, kp, (long)HID * NPIX,
                                    nullptr, HID, NPIX, NC, 1.0f);
    sgemm128_kernel<<<gproj, 256>>>(Wv, 0, cin, (long)NC * NPIX, vp, (long)HID * NPIX,
                                    nullptr, HID, NPIX, NC, 1.0f);

    // softmax stats over m for each k row
    softmax_stats_kernel<<<NB * HID, 256>>>(kp, rm, ri);

    // ctx = softmax(k) @ v^T per (b,h), split-K over m
    dim3 gctx(NB * NHEAD, NCHUNK);
    ctx_partial_kernel<<<gctx, 256>>>(kp, vp, rm, ri, pt);

    // reduce partials + fold Wo into ctx
    fold_kernel<<<NB * NHEAD, 256>>>(Wo, pt, fd);

    // combined[b] = fold[b] @ (scale * Wq)   (256x256, K=512)
    dim3 gcomb(NC / 64, NC / 64, NB);
    sgemm64_kernel<<<gcomb, 256>>>(fd, (long)NC * HID, Wq, 0, cb, (long)NC * NC,
                                   nullptr, NC, NC, HID, scale);

    // out = combined @ x + bo   (per batch, K=256)
    dim3 gfin(NPIX / 128, NC / 128, NB);
    sgemm128_kernel<<<gfin, 256>>>(cb, (long)NC * NC, x, (long)NC * NPIX,
                                   out, (long)NC * NPIX, bo, NC, NPIX, NC, 1.0f);
}

// round 4
// speedup vs baseline: 3.7179x; 2.0373x over previous
#include <cuda_runtime.h>
#include <math.h>
#include <stdint.h>

#define NB    8
#define NC    256
#define HID   512
#define NPIX  4096
#define NHEAD 8
#define DHEAD 64
#define NCHUNK 16
#define PART_LD 65
#define PART_BH (DHEAD * PART_LD)   // 4160

// ---------------- scratch ----------------
__device__ __align__(256) float g_kv[NB * 1024 * NPIX];                       // 134 MB (k rows 0-511, v rows 512-1023)
__device__ __align__(256) float g_wkv[1024 * NC];                             // 1 MB
__device__ __align__(256) float g_part[NCHUNK * NB * NHEAD * PART_BH];        // 17 MB
__device__ __align__(256) float g_fold[NB * NC * HID];                        // 4 MB
__device__ __align__(256) float g_comb[NB * NC * NC];                         // 2 MB

// ---------------- helpers ----------------
__device__ __forceinline__ uint32_t f2tf32(float f) {
    uint32_t u;
    asm("cvt.rna.tf32.f32 %0, %1;" : "=r"(u) : "f"(f));
    return u;
}

__device__ __forceinline__ void mma_tf32(float* d, const uint32_t* a, const uint32_t* b) {
    asm volatile(
        "mma.sync.aligned.m16n8k8.row.col.f32.tf32.tf32.f32 "
        "{%0,%1,%2,%3}, {%4,%5,%6,%7}, {%8,%9}, {%0,%1,%2,%3};"
        : "+f"(d[0]), "+f"(d[1]), "+f"(d[2]), "+f"(d[3])
        : "r"(a[0]), "r"(a[1]), "r"(a[2]), "r"(a[3]), "r"(b[0]), "r"(b[1]));
}

// ---------------- pack Wk;Wv ----------------
__global__ void pack_wkv(const float* __restrict__ Wk, const float* __restrict__ Wv,
                         float* __restrict__ Wkv)
{
    const int i = blockIdx.x * 256 + threadIdx.x;   // 0 .. 512*256-1
    Wkv[i] = Wk[i];
    Wkv[HID * NC + i] = Wv[i];
}

// ---------------- tf32 mma.sync GEMM: C = alpha*A@B + bias[m] ----------------
// A: MxK rm (lda, batch stride sA; 0=shared). B: KxN rm (ldb, sB). C: MxN rm (ldc, sC).
// Tile 128x128x32, 256 threads, 8 warps in 2(m) x 4(n), warp tile 64x32.
__global__ __launch_bounds__(256, 2)
void mma_gemm(const float* __restrict__ A, long sA, int lda,
              const float* __restrict__ B, long sB, int ldb,
              float* __restrict__ C, long sC, int ldc,
              const float* __restrict__ bias, int K, float alpha)
{
    __shared__ uint32_t As[128][36];   // [m][k], pad -> bank (4g+t) conflict-free
    __shared__ uint32_t Bs[32][136];   // [k][n], pad -> bank (8t+g) conflict-free

    const int bb = blockIdx.z;
    A += (size_t)bb * sA;
    B += (size_t)bb * sB;
    C += (size_t)bb * sC;

    const int tid = threadIdx.x;
    const int wid = tid >> 5, lid = tid & 31;
    const int g = lid >> 2, t = lid & 3;
    const int wm = (wid >> 2) * 64, wn = (wid & 3) * 32;
    const int m0 = blockIdx.y * 128, n0 = blockIdx.x * 128;

    // loaders
    const int am = tid >> 1;           // A row
    const int as = tid & 1;            // A float4 slot base
    const int bk = tid >> 3;           // B k-row
    const int bn = (tid & 7) * 4;      // B n base

    float acc[4][4][4];
    #pragma unroll
    for (int i = 0; i < 4; i++)
        #pragma unroll
        for (int j = 0; j < 4; j++)
            #pragma unroll
            for (int q = 0; q < 4; q++) acc[i][j][q] = 0.0f;

    const int KT = K >> 5;
    for (int kt = 0; kt < KT; kt++) {
        const int k0 = kt << 5;
        #pragma unroll
        for (int p = 0; p < 4; p++) {
            const int kf = (as + 2 * p) * 4;
            float4 a = *(const float4*)(A + (size_t)(m0 + am) * lda + k0 + kf);
            As[am][kf + 0] = f2tf32(a.x);
            As[am][kf + 1] = f2tf32(a.y);
            As[am][kf + 2] = f2tf32(a.z);
            As[am][kf + 3] = f2tf32(a.w);
        }
        #pragma unroll
        for (int p = 0; p < 4; p++) {
            const int nf = bn + 32 * p;
            float4 b = *(const float4*)(B + (size_t)(k0 + bk) * ldb + n0 + nf);
            Bs[bk][nf + 0] = f2tf32(b.x);
            Bs[bk][nf + 1] = f2tf32(b.y);
            Bs[bk][nf + 2] = f2tf32(b.z);
            Bs[bk][nf + 3] = f2tf32(b.w);
        }
        __syncthreads();

        #pragma unroll
        for (int ks = 0; ks < 4; ks++) {
            const int kk = ks * 8;
            uint32_t af[4][4], bf[4][2];
            #pragma unroll
            for (int i = 0; i < 4; i++) {
                const int r = wm + i * 16 + g;
                af[i][0] = As[r][kk + t];
                af[i][1] = As[r + 8][kk + t];
                af[i][2] = As[r][kk + t + 4];
                af[i][3] = As[r + 8][kk + t + 4];
            }
            #pragma unroll
            for (int j = 0; j < 4; j++) {
                const int c = wn + j * 8 + g;
                bf[j][0] = Bs[kk + t][c];
                bf[j][1] = Bs[kk + t + 4][c];
            }
            #pragma unroll
            for (int i = 0; i < 4; i++)
                #pragma unroll
                for (int j = 0; j < 4; j++)
                    mma_tf32(acc[i][j], af[i], bf[j]);
        }
        __syncthreads();
    }

    // epilogue
    #pragma unroll
    for (int i = 0; i < 4; i++) {
        const int r0 = m0 + wm + i * 16 + g;
        const int r1 = r0 + 8;
        const float bi0 = bias ? bias[r0] : 0.0f;
        const float bi1 = bias ? bias[r1] : 0.0f;
        #pragma unroll
        for (int j = 0; j < 4; j++) {
            const int col = n0 + wn + j * 8 + 2 * t;
            float2 o0 = make_float2(acc[i][j][0] * alpha + bi0, acc[i][j][1] * alpha + bi0);
            float2 o1 = make_float2(acc[i][j][2] * alpha + bi1, acc[i][j][3] * alpha + bi1);
            *(float2*)(C + (size_t)r0 * ldc + col) = o0;
            *(float2*)(C + (size_t)r1 * ldc + col) = o1;
        }
    }
}

// ---------------- ctx partial (split-K over m) with inline exp + row-sum ----------------
// part[ch][bh][d][e<64] = sum_{m in chunk} exp(k[d,m]) * v[e,m];  part[..][d][64] = sum exp
__global__ void ctx_partial_kernel(const float* __restrict__ KV, float* __restrict__ part)
{
    const int bh = blockIdx.x;
    const int ch = blockIdx.y;
    const int b = bh >> 3, h = bh & 7;
    const float* kp = KV + (size_t)b * 1024 * NPIX + (size_t)(h * 64) * NPIX;
    const float* vp = KV + (size_t)b * 1024 * NPIX + (size_t)(512 + h * 64) * NPIX;

    __shared__ float As[32][65];
    __shared__ float Bs[32][65];

    const int tid = threadIdx.x;
    const int tx = tid & 15, ty = tid >> 4;
    const int d  = tid >> 2;
    const int m8 = (tid & 3) << 3;

    float acc[4][4] = {};
    float es = 0.0f;
    const int mbeg = ch * (NPIX / NCHUNK);
    const int mend = mbeg + (NPIX / NCHUNK);

    for (int m0 = mbeg; m0 < mend; m0 += 32) {
        const float* krow = kp + (size_t)d * NPIX + m0 + m8;
        const float* vrow = vp + (size_t)d * NPIX + m0 + m8;
        float4 a0 = *(const float4*)(krow);
        float4 a1 = *(const float4*)(krow + 4);
        float e0 = expf(a0.x), e1 = expf(a0.y), e2 = expf(a0.z), e3 = expf(a0.w);
        float e4 = expf(a1.x), e5 = expf(a1.y), e6 = expf(a1.z), e7 = expf(a1.w);
        As[m8 + 0][d] = e0; As[m8 + 1][d] = e1; As[m8 + 2][d] = e2; As[m8 + 3][d] = e3;
        As[m8 + 4][d] = e4; As[m8 + 5][d] = e5; As[m8 + 6][d] = e6; As[m8 + 7][d] = e7;
        es += (e0 + e1) + (e2 + e3) + ((e4 + e5) + (e6 + e7));
        float4 b0 = *(const float4*)(vrow);
        float4 b1 = *(const float4*)(vrow + 4);
        Bs[m8 + 0][d] = b0.x; Bs[m8 + 1][d] = b0.y;
        Bs[m8 + 2][d] = b0.z; Bs[m8 + 3][d] = b0.w;
        Bs[m8 + 4][d] = b1.x; Bs[m8 + 5][d] = b1.y;
        Bs[m8 + 6][d] = b1.z; Bs[m8 + 7][d] = b1.w;

        __syncthreads();

        #pragma unroll
        for (int kk = 0; kk < 32; kk++) {
            float ar[4], br[4];
            #pragma unroll
            for (int i = 0; i < 4; i++) ar[i] = As[kk][ty * 4 + i];
            #pragma unroll
            for (int j = 0; j < 4; j++) br[j] = Bs[kk][tx * 4 + j];
            #pragma unroll
            for (int i = 0; i < 4; i++)
                #pragma unroll
                for (int j = 0; j < 4; j++)
                    acc[i][j] += ar[i] * br[j];
        }
        __syncthreads();
    }

    float* cp = part + ((size_t)ch * 64 + bh) * PART_BH;
    #pragma unroll
    for (int i = 0; i < 4; i++)
        #pragma unroll
        for (int j = 0; j < 4; j++)
            cp[(ty * 4 + i) * PART_LD + tx * 4 + j] = acc[i][j];

    // reduce exp-sums across the 4 threads sharing row d (lanes 4d..4d+3)
    es += __shfl_xor_sync(0xffffffffu, es, 1);
    es += __shfl_xor_sync(0xffffffffu, es, 2);
    if ((tid & 3) == 0) cp[d * PART_LD + 64] = es;
}

// ---------------- reduce partials, normalize, fold Wo ----------------
__global__ void fold_kernel(const float* __restrict__ Wo, const float* __restrict__ part,
                            float* __restrict__ fold)
{
    const int bh = blockIdx.x;
    const int b = bh >> 3, h = bh & 7;

    __shared__ float cs[64][64];
    __shared__ float Sd[64];

    const int tid = threadIdx.x;
    if (tid < 64) {
        float s = 0.0f;
        #pragma unroll
        for (int ch = 0; ch < NCHUNK; ch++)
            s += part[((size_t)ch * 64 + bh) * PART_BH + tid * PART_LD + 64];
        Sd[tid] = 1.0f / s;
    }
    __syncthreads();

    for (int i = tid; i < 4096; i += 256) {
        const int dd = i >> 6, e = i & 63;
        float s = 0.0f;
        #pragma unroll
        for (int ch = 0; ch < NCHUNK; ch++)
            s += part[((size_t)ch * 64 + bh) * PART_BH + dd * PART_LD + e];
        cs[dd][e] = s * Sd[dd];
    }
    __syncthreads();

    const int o = tid;  // 0..255
    float w[64];
    #pragma unroll
    for (int e = 0; e < 64; e++) w[e] = Wo[(size_t)o * HID + h * 64 + e];

    float* fp = fold + ((size_t)b * NC + o) * HID + h * 64;
    for (int dd = 0; dd < 64; dd++) {
        float s = 0.0f;
        #pragma unroll
        for (int e = 0; e < 64; e++) s += w[e] * cs[dd][e];
        fp[dd] = s;
    }
}

// ---------------- launch ----------------
extern "C" void kernel_launch(void* const* d_in, const int* in_sizes, int n_in,
                              void* d_out, int out_size)
{
    const float* x    = (const float*)d_in[0];
    const float* cin  = (const float*)d_in[1];
    const float* Wq   = (const float*)d_in[2];
    const float* Wk   = (const float*)d_in[3];
    const float* Wv   = (const float*)d_in[4];
    const float* Wo   = (const float*)d_in[5];
    const float* bo   = (const float*)d_in[6];
    float* out = (float*)d_out;

    float *kv, *wkv, *pt, *fd, *cb;
    cudaGetSymbolAddress((void**)&kv, g_kv);
    cudaGetSymbolAddress((void**)&wkv, g_wkv);
    cudaGetSymbolAddress((void**)&pt, g_part);
    cudaGetSymbolAddress((void**)&fd, g_fold);
    cudaGetSymbolAddress((void**)&cb, g_comb);

    const float scale = 0.125f;  // 64^-0.5

    // pack [Wk; Wv] -> 1024 x 256
    pack_wkv<<<HID * NC / 256, 256>>>(Wk, Wv, wkv);

    // kv = Wkv @ cin  (per batch; M=1024, N=4096, K=256)
    dim3 gproj(NPIX / 128, 1024 / 128, NB);
    mma_gemm<<<gproj, 256>>>(wkv, 0, NC, cin, (long)NC * NPIX, NPIX,
                             kv, (long)1024 * NPIX, NPIX, nullptr, NC, 1.0f);

    // ctx partials (exp + row-sum fused)
    dim3 gctx(NB * NHEAD, NCHUNK);
    ctx_partial_kernel<<<gctx, 256>>>(kv, pt);

    // reduce + normalize + fold Wo
    fold_kernel<<<NB * NHEAD, 256>>>(Wo, pt, fd);

    // comb[b] = fold[b] @ (scale*Wq)   (M=256, N=256, K=512)
    dim3 gcomb(NC / 128, NC / 128, NB);
    mma_gemm<<<gcomb, 256>>>(fd, (long)NC * HID, HID, Wq, 0, NC,
                             cb, (long)NC * NC, NC, nullptr, HID, scale);

    // out = comb @ x + bo   (M=256, N=4096, K=256)
    dim3 gfin(NPIX / 128, NC / 128, NB);
    mma_gemm<<<gfin, 256>>>(cb, (long)NC * NC, NC, x, (long)NC * NPIX, NPIX,
                            out, (long)NC * NPIX, NPIX, bo, NC, 1.0f);
}

// round 5
// speedup vs baseline: 4.2524x; 1.1438x over previous
#include <cuda_runtime.h>
#include <math.h>
#include <stdint.h>

#define NB    8
#define NC    256
#define HID   512
#define NPIX  4096
#define NHEAD 8
#define DHEAD 64
#define NCHUNK 16
#define PART_LD 65
#define PART_BH (DHEAD * PART_LD)   // 4160

// ---------------- scratch ----------------
__device__ __align__(256) float g_kv[NB * 1024 * NPIX];                 // k rows 0-511, v rows 512-1023
__device__ __align__(256) float g_wkv[1024 * NC];
__device__ __align__(256) float g_part[NCHUNK * NB * NHEAD * PART_BH];
__device__ __align__(256) float g_fold[NB * NC * HID];
__device__ __align__(256) float g_comb[NB * NC * NC];

// ---------------- helpers ----------------
__device__ __forceinline__ uint32_t f2tf32(float f) {
    uint32_t u;
    asm("cvt.rna.tf32.f32 %0, %1;" : "=r"(u) : "f"(f));
    return u;
}

__device__ __forceinline__ void mma_tf32(float* d, const uint32_t* a, const uint32_t* b) {
    asm volatile(
        "mma.sync.aligned.m16n8k8.row.col.f32.tf32.tf32.f32 "
        "{%0,%1,%2,%3}, {%4,%5,%6,%7}, {%8,%9}, {%0,%1,%2,%3};"
        : "+f"(d[0]), "+f"(d[1]), "+f"(d[2]), "+f"(d[3])
        : "r"(a[0]), "r"(a[1]), "r"(a[2]), "r"(a[3]), "r"(b[0]), "r"(b[1]));
}

// ---------------- pack Wk;Wv ----------------
__global__ void pack_wkv(const float* __restrict__ Wk, const float* __restrict__ Wv,
                         float* __restrict__ Wkv)
{
    const int i = blockIdx.x * 256 + threadIdx.x;
    Wkv[i] = Wk[i];
    Wkv[HID * NC + i] = Wv[i];
}

// ---------------- tf32 mma.sync GEMM: C = alpha*A@B + bias[m] ----------------
__global__ __launch_bounds__(256, 2)
void mma_gemm(const float* __restrict__ A, long sA, int lda,
              const float* __restrict__ B, long sB, int ldb,
              float* __restrict__ C, long sC, int ldc,
              const float* __restrict__ bias, int K, float alpha)
{
    __shared__ uint32_t As[128][36];
    __shared__ uint32_t Bs[32][136];

    const int bb = blockIdx.z;
    A += (size_t)bb * sA;
    B += (size_t)bb * sB;
    C += (size_t)bb * sC;

    const int tid = threadIdx.x;
    const int wid = tid >> 5, lid = tid & 31;
    const int g = lid >> 2, t = lid & 3;
    const int wm = (wid >> 2) * 64, wn = (wid & 3) * 32;
    const int m0 = blockIdx.y * 128, n0 = blockIdx.x * 128;

    const int am = tid >> 1;
    const int as = tid & 1;
    const int bk = tid >> 3;
    const int bn = (tid & 7) * 4;

    float acc[4][4][4];
    #pragma unroll
    for (int i = 0; i < 4; i++)
        #pragma unroll
        for (int j = 0; j < 4; j++)
            #pragma unroll
            for (int q = 0; q < 4; q++) acc[i][j][q] = 0.0f;

    const int KT = K >> 5;
    for (int kt = 0; kt < KT; kt++) {
        const int k0 = kt << 5;
        #pragma unroll
        for (int p = 0; p < 4; p++) {
            const int kf = (as + 2 * p) * 4;
            float4 a = *(const float4*)(A + (size_t)(m0 + am) * lda + k0 + kf);
            As[am][kf + 0] = f2tf32(a.x);
            As[am][kf + 1] = f2tf32(a.y);
            As[am][kf + 2] = f2tf32(a.z);
            As[am][kf + 3] = f2tf32(a.w);
        }
        #pragma unroll
        for (int p = 0; p < 4; p++) {
            const int nf = bn + 32 * p;
            float4 b = *(const float4*)(B + (size_t)(k0 + bk) * ldb + n0 + nf);
            Bs[bk][nf + 0] = f2tf32(b.x);
            Bs[bk][nf + 1] = f2tf32(b.y);
            Bs[bk][nf + 2] = f2tf32(b.z);
            Bs[bk][nf + 3] = f2tf32(b.w);
        }
        __syncthreads();

        #pragma unroll
        for (int ks = 0; ks < 4; ks++) {
            const int kk = ks * 8;
            uint32_t af[4][4], bf[4][2];
            #pragma unroll
            for (int i = 0; i < 4; i++) {
                const int r = wm + i * 16 + g;
                af[i][0] = As[r][kk + t];
                af[i][1] = As[r + 8][kk + t];
                af[i][2] = As[r][kk + t + 4];
                af[i][3] = As[r + 8][kk + t + 4];
            }
            #pragma unroll
            for (int j = 0; j < 4; j++) {
                const int c = wn + j * 8 + g;
                bf[j][0] = Bs[kk + t][c];
                bf[j][1] = Bs[kk + t + 4][c];
            }
            #pragma unroll
            for (int i = 0; i < 4; i++)
                #pragma unroll
                for (int j = 0; j < 4; j++)
                    mma_tf32(acc[i][j], af[i], bf[j]);
        }
        __syncthreads();
    }

    #pragma unroll
    for (int i = 0; i < 4; i++) {
        const int r0 = m0 + wm + i * 16 + g;
        const int r1 = r0 + 8;
        const float bi0 = bias ? bias[r0] : 0.0f;
        const float bi1 = bias ? bias[r1] : 0.0f;
        #pragma unroll
        for (int j = 0; j < 4; j++) {
            const int col = n0 + wn + j * 8 + 2 * t;
            float2 o0 = make_float2(acc[i][j][0] * alpha + bi0, acc[i][j][1] * alpha + bi0);
            float2 o1 = make_float2(acc[i][j][2] * alpha + bi1, acc[i][j][3] * alpha + bi1);
            *(float2*)(C + (size_t)r0 * ldc + col) = o0;
            *(float2*)(C + (size_t)r1 * ldc + col) = o1;
        }
    }
}

// ---------------- ctx partial via tf32 mma (NT GEMM with fused exp) ----------------
// part[ch][bh][d][e<64] = sum_{m in chunk} exp(k[d,m]) * v[e,m];  part[..][d][64] = sum exp
__global__ __launch_bounds__(256)
void ctx_partial_kernel(const float* __restrict__ KV, float* __restrict__ part)
{
    const int bh = blockIdx.x;
    const int ch = blockIdx.y;
    const int b = bh >> 3, h = bh & 7;
    const float* kp = KV + (size_t)b * 1024 * NPIX + (size_t)(h * 64) * NPIX;
    const float* vp = KV + (size_t)b * 1024 * NPIX + (size_t)(512 + h * 64) * NPIX;

    __shared__ uint32_t As[64][36];   // exp(k) tf32, [d][m]
    __shared__ uint32_t Bs[64][36];   // v tf32, [e][m]

    const int tid = threadIdx.x;
    const int wid = tid >> 5, lid = tid & 31;
    const int g = lid >> 2, t = lid & 3;
    const int wm = (wid & 3) * 16, wn = (wid >> 2) * 32;

    const int d  = tid >> 2;         // loader row 0..63
    const int m8 = (tid & 3) << 3;   // 0,8,16,24

    float acc[4][4];
    #pragma unroll
    for (int j = 0; j < 4; j++)
        #pragma unroll
        for (int q = 0; q < 4; q++) acc[j][q] = 0.0f;

    float es = 0.0f;
    const int mbeg = ch * (NPIX / NCHUNK);
    const int mend = mbeg + (NPIX / NCHUNK);

    for (int m0 = mbeg; m0 < mend; m0 += 32) {
        const float* krow = kp + (size_t)d * NPIX + m0 + m8;
        const float* vrow = vp + (size_t)d * NPIX + m0 + m8;
        float4 a0 = *(const float4*)(krow);
        float4 a1 = *(const float4*)(krow + 4);
        float e0 = expf(a0.x), e1 = expf(a0.y), e2 = expf(a0.z), e3 = expf(a0.w);
        float e4 = expf(a1.x), e5 = expf(a1.y), e6 = expf(a1.z), e7 = expf(a1.w);
        As[d][m8 + 0] = f2tf32(e0); As[d][m8 + 1] = f2tf32(e1);
        As[d][m8 + 2] = f2tf32(e2); As[d][m8 + 3] = f2tf32(e3);
        As[d][m8 + 4] = f2tf32(e4); As[d][m8 + 5] = f2tf32(e5);
        As[d][m8 + 6] = f2tf32(e6); As[d][m8 + 7] = f2tf32(e7);
        es += (e0 + e1) + (e2 + e3) + ((e4 + e5) + (e6 + e7));
        float4 b0 = *(const float4*)(vrow);
        float4 b1 = *(const float4*)(vrow + 4);
        Bs[d][m8 + 0] = f2tf32(b0.x); Bs[d][m8 + 1] = f2tf32(b0.y);
        Bs[d][m8 + 2] = f2tf32(b0.z); Bs[d][m8 + 3] = f2tf32(b0.w);
        Bs[d][m8 + 4] = f2tf32(b1.x); Bs[d][m8 + 5] = f2tf32(b1.y);
        Bs[d][m8 + 6] = f2tf32(b1.z); Bs[d][m8 + 7] = f2tf32(b1.w);

        __syncthreads();

        #pragma unroll
        for (int ks = 0; ks < 4; ks++) {
            const int kk = ks * 8;
            uint32_t af[4], bf[4][2];
            af[0] = As[wm + g][kk + t];
            af[1] = As[wm + g + 8][kk + t];
            af[2] = As[wm + g][kk + t + 4];
            af[3] = As[wm + g + 8][kk + t + 4];
            #pragma unroll
            for (int j = 0; j < 4; j++) {
                const int c = wn + j * 8 + g;
                bf[j][0] = Bs[c][kk + t];
                bf[j][1] = Bs[c][kk + t + 4];
            }
            #pragma unroll
            for (int j = 0; j < 4; j++)
                mma_tf32(acc[j], af, bf[j]);
        }
        __syncthreads();
    }

    float* cp = part + ((size_t)ch * 64 + bh) * PART_BH;
    const int r0 = wm + g, r1 = wm + g + 8;
    #pragma unroll
    for (int j = 0; j < 4; j++) {
        const int c = wn + j * 8 + 2 * t;
        cp[r0 * PART_LD + c]     = acc[j][0];
        cp[r0 * PART_LD + c + 1] = acc[j][1];
        cp[r1 * PART_LD + c]     = acc[j][2];
        cp[r1 * PART_LD + c + 1] = acc[j][3];
    }

    // reduce exp-sums across the 4 loader threads of row d
    es += __shfl_xor_sync(0xffffffffu, es, 1);
    es += __shfl_xor_sync(0xffffffffu, es, 2);
    if ((tid & 3) == 0) cp[d * PART_LD + 64] = es;
}

// ---------------- reduce partials, normalize, fold Wo (4-way split over d) ----------------
__global__ void fold_kernel(const float* __restrict__ Wo, const float* __restrict__ part,
                            float* __restrict__ fold)
{
    const int bh = blockIdx.x;
    const int qd = blockIdx.y;          // which 16-row slab of d
    const int b = bh >> 3, h = bh & 7;
    const int dd0 = qd * 16;

    __shared__ float cs[16][64];
    __shared__ float Sd[16];

    const int tid = threadIdx.x;
    if (tid < 16) {
        float s = 0.0f;
        #pragma unroll
        for (int ch = 0; ch < NCHUNK; ch++)
            s += part[((size_t)ch * 64 + bh) * PART_BH + (dd0 + tid) * PART_LD + 64];
        Sd[tid] = 1.0f / s;
    }
    __syncthreads();

    for (int i = tid; i < 1024; i += 256) {
        const int dd = i >> 6, e = i & 63;
        float s = 0.0f;
        #pragma unroll
        for (int ch = 0; ch < NCHUNK; ch++)
            s += part[((size_t)ch * 64 + bh) * PART_BH + (dd0 + dd) * PART_LD + e];
        cs[dd][e] = s * Sd[dd];
    }
    __syncthreads();

    const int o = tid;
    float w[64];
    #pragma unroll
    for (int e = 0; e < 64; e++) w[e] = Wo[(size_t)o * HID + h * 64 + e];

    float* fp = fold + ((size_t)b * NC + o) * HID + h * 64 + dd0;
    #pragma unroll
    for (int dd = 0; dd < 16; dd++) {
        float s = 0.0f;
        #pragma unroll
        for (int e = 0; e < 64; e++) s += w[e] * cs[dd][e];
        fp[dd] = s;
    }
}

// ---------------- launch ----------------
extern "C" void kernel_launch(void* const* d_in, const int* in_sizes, int n_in,
                              void* d_out, int out_size)
{
    const float* x    = (const float*)d_in[0];
    const float* cin  = (const float*)d_in[1];
    const float* Wq   = (const float*)d_in[2];
    const float* Wk   = (const float*)d_in[3];
    const float* Wv   = (const float*)d_in[4];
    const float* Wo   = (const float*)d_in[5];
    const float* bo   = (const float*)d_in[6];
    float* out = (float*)d_out;

    float *kv, *wkv, *pt, *fd, *cb;
    cudaGetSymbolAddress((void**)&kv, g_kv);
    cudaGetSymbolAddress((void**)&wkv, g_wkv);
    cudaGetSymbolAddress((void**)&pt, g_part);
    cudaGetSymbolAddress((void**)&fd, g_fold);
    cudaGetSymbolAddress((void**)&cb, g_comb);

    const float scale = 0.125f;

    pack_wkv<<<HID * NC / 256, 256>>>(Wk, Wv, wkv);

    // kv = Wkv @ cin  (M=1024, N=4096, K=256 per batch)
    dim3 gproj(NPIX / 128, 1024 / 128, NB);
    mma_gemm<<<gproj, 256>>>(wkv, 0, NC, cin, (long)NC * NPIX, NPIX,
                             kv, (long)1024 * NPIX, NPIX, nullptr, NC, 1.0f);

    // ctx partials (tensor-core NT GEMM, fused exp + row-sum)
    dim3 gctx(NB * NHEAD, NCHUNK);
    ctx_partial_kernel<<<gctx, 256>>>(kv, pt);

    // reduce + normalize + fold Wo
    dim3 gfold(NB * NHEAD, 4);
    fold_kernel<<<gfold, 256>>>(Wo, pt, fd);

    // comb[b] = fold[b] @ (scale*Wq)   (M=256, N=256, K=512)
    dim3 gcomb(NC / 128, NC / 128, NB);
    mma_gemm<<<gcomb, 256>>>(fd, (long)NC * HID, HID, Wq, 0, NC,
                             cb, (long)NC * NC, NC, nullptr, HID, scale);

    // out = comb @ x + bo   (M=256, N=4096, K=256)
    dim3 gfin(NPIX / 128, NC / 128, NB);
    mma_gemm<<<gfin, 256>>>(cb, (long)NC * NC, NC, x, (long)NC * NPIX, NPIX,
                            out, (long)NC * NPIX, NPIX, bo, NC, 1.0f);
}

// round 6
// speedup vs baseline: 5.5211x; 1.2984x over previous
#include <cuda_runtime.h>
#include <cuda_fp16.h>
#include <math.h>
#include <stdint.h>

#define NB    8
#define NC    256
#define HID   512
#define NPIX  4096
#define NHEAD 8
#define DHEAD 64
#define NCHUNK 8
#define PART_LD 68
#define PART_BH (DHEAD * PART_LD)   // 4352

// ---------------- scratch ----------------
__device__ __align__(256) __half g_kvh[NB * 1024 * NPIX];               // 67 MB: rows 0-511 = exp(k), 512-1023 = v
__device__ __align__(256) float g_wkv[1024 * NC];
__device__ __align__(256) float g_part[NCHUNK * NB * NHEAD * PART_BH];  // 8.9 MB
__device__ __align__(256) float g_fold[NB * NC * HID];
__device__ __align__(256) float g_comb[NB * NC * NC];

// ---------------- helpers ----------------
__device__ __forceinline__ void mma_f16(float* d, const uint32_t* a, const uint32_t* b) {
    asm volatile(
        "mma.sync.aligned.m16n8k16.row.col.f32.f16.f16.f32 "
        "{%0,%1,%2,%3}, {%4,%5,%6,%7}, {%8,%9}, {%0,%1,%2,%3};"
        : "+f"(d[0]), "+f"(d[1]), "+f"(d[2]), "+f"(d[3])
        : "r"(a[0]), "r"(a[1]), "r"(a[2]), "r"(a[3]), "r"(b[0]), "r"(b[1]));
}

// ---------------- pack Wk;Wv ----------------
__global__ void pack_wkv(const float* __restrict__ Wk, const float* __restrict__ Wv,
                         float* __restrict__ Wkv)
{
    const int i = blockIdx.x * 256 + threadIdx.x;
    Wkv[i] = Wk[i];
    Wkv[HID * NC + i] = Wv[i];
}

// ---------------- fp16 mma GEMM ----------------
// A: MxK rm fp32 (lda, sA; 0=shared). B: KxN rm fp32 (ldb, sB).
// mode 0: C fp32, C = alpha*A@B + bias[m]
// mode 1: C half; rows with m0<512 get exp() applied (proj k rows), no alpha/bias
// Tile 128x128x32, 256 threads, 8 warps 2(m) x 4(n), warp tile 64x32.
__global__ __launch_bounds__(256, 2)
void mma_gemm(const float* __restrict__ A, long sA, int lda,
              const float* __restrict__ B, long sB, int ldb,
              void* __restrict__ Cv, long sC, int ldc,
              const float* __restrict__ bias, int K, float alpha, int mode)
{
    __shared__ uint32_t As32[128][20];   // [m][k2], half2 along k
    __shared__ uint32_t Bs32[16][136];   // [k2][n], half2 along k

    const int bb = blockIdx.z;
    A += (size_t)bb * sA;
    B += (size_t)bb * sB;

    const int tid = threadIdx.x;
    const int wid = tid >> 5, lid = tid & 31;
    const int g = lid >> 2, t = lid & 3;
    const int wm = (wid >> 2) * 64, wn = (wid & 3) * 32;
    const int m0 = blockIdx.y * 128, n0 = blockIdx.x * 128;

    const int am = tid >> 1;
    const int as = tid & 1;
    const int bk = tid >> 3;
    const int bn = (tid & 7) * 4;

    float acc[4][4][4];
    #pragma unroll
    for (int i = 0; i < 4; i++)
        #pragma unroll
        for (int j = 0; j < 4; j++)
            #pragma unroll
            for (int q = 0; q < 4; q++) acc[i][j][q] = 0.0f;

    __half* bsh = (__half*)&Bs32[0][0];

    const int KT = K >> 5;
    for (int kt = 0; kt < KT; kt++) {
        const int k0 = kt << 5;
        #pragma unroll
        for (int p = 0; p < 4; p++) {
            const int kf = (as + 2 * p) * 4;
            float4 a = *(const float4*)(A + (size_t)(m0 + am) * lda + k0 + kf);
            *(__half2*)&As32[am][kf / 2 + 0] = __floats2half2_rn(a.x, a.y);
            *(__half2*)&As32[am][kf / 2 + 1] = __floats2half2_rn(a.z, a.w);
        }
        #pragma unroll
        for (int p = 0; p < 4; p++) {
            const int nf = bn + 32 * p;
            float4 b = *(const float4*)(B + (size_t)(k0 + bk) * ldb + n0 + nf);
            const int base = (bk >> 1) * 272 + (bk & 1);
            bsh[base + 2 * (nf + 0)] = __float2half_rn(b.x);
            bsh[base + 2 * (nf + 1)] = __float2half_rn(b.y);
            bsh[base + 2 * (nf + 2)] = __float2half_rn(b.z);
            bsh[base + 2 * (nf + 3)] = __float2half_rn(b.w);
        }
        __syncthreads();

        #pragma unroll
        for (int ks = 0; ks < 2; ks++) {
            const int kk2 = ks * 8;
            uint32_t af[4][4], bf[4][2];
            #pragma unroll
            for (int i = 0; i < 4; i++) {
                const int r = wm + i * 16 + g;
                af[i][0] = As32[r][kk2 + t];
                af[i][1] = As32[r + 8][kk2 + t];
                af[i][2] = As32[r][kk2 + t + 4];
                af[i][3] = As32[r + 8][kk2 + t + 4];
            }
            #pragma unroll
            for (int j = 0; j < 4; j++) {
                const int c = wn + j * 8 + g;
                bf[j][0] = Bs32[kk2 + t][c];
                bf[j][1] = Bs32[kk2 + t + 4][c];
            }
            #pragma unroll
            for (int i = 0; i < 4; i++)
                #pragma unroll
                for (int j = 0; j < 4; j++)
                    mma_f16(acc[i][j], af[i], bf[j]);
        }
        __syncthreads();
    }

    if (mode == 0) {
        float* C = (float*)Cv + (size_t)bb * sC;
        #pragma unroll
        for (int i = 0; i < 4; i++) {
            const int r0 = m0 + wm + i * 16 + g;
            const int r1 = r0 + 8;
            const float bi0 = bias ? bias[r0] : 0.0f;
            const float bi1 = bias ? bias[r1] : 0.0f;
            #pragma unroll
            for (int j = 0; j < 4; j++) {
                const int col = n0 + wn + j * 8 + 2 * t;
                float2 o0 = make_float2(acc[i][j][0] * alpha + bi0, acc[i][j][1] * alpha + bi0);
                float2 o1 = make_float2(acc[i][j][2] * alpha + bi1, acc[i][j][3] * alpha + bi1);
                *(float2*)(C + (size_t)r0 * ldc + col) = o0;
                *(float2*)(C + (size_t)r1 * ldc + col) = o1;
            }
        }
    } else {
        __half* C = (__half*)Cv + (size_t)bb * sC;
        const bool doexp = (m0 < 512);
        #pragma unroll
        for (int i = 0; i < 4; i++) {
            const int r0 = m0 + wm + i * 16 + g;
            const int r1 = r0 + 8;
            #pragma unroll
            for (int j = 0; j < 4; j++) {
                const int col = n0 + wn + j * 8 + 2 * t;
                float4 v = make_float4(acc[i][j][0], acc[i][j][1], acc[i][j][2], acc[i][j][3]);
                if (doexp) {
                    v.x = expf(v.x); v.y = expf(v.y); v.z = expf(v.z); v.w = expf(v.w);
                }
                *(__half2*)(C + (size_t)r0 * ldc + col) = __floats2half2_rn(v.x, v.y);
                *(__half2*)(C + (size_t)r1 * ldc + col) = __floats2half2_rn(v.z, v.w);
            }
        }
    }
}

// ---------------- ctx partial via fp16 mma (NT, data already half) ----------------
// part[ch][bh][d][e<64] = sum_{m in chunk} expk[d,m] * v[e,m];  [..][d][64] = sum expk
__global__ __launch_bounds__(256)
void ctx_partial_kernel(const __half* __restrict__ KVh, float* __restrict__ part)
{
    const int bh = blockIdx.x;
    const int ch = blockIdx.y;
    const int b = bh >> 3, h = bh & 7;
    const __half* kp = KVh + (size_t)b * 1024 * NPIX + (size_t)(h * 64) * NPIX;
    const __half* vp = KVh + (size_t)b * 1024 * NPIX + (size_t)(512 + h * 64) * NPIX;

    __shared__ uint32_t As32[64][20];   // expk [d][m2]
    __shared__ uint32_t Bs32[64][20];   // v    [e][m2]

    const int tid = threadIdx.x;
    const int wid = tid >> 5, lid = tid & 31;
    const int g = lid >> 2, t = lid & 3;
    const int wm = (wid & 3) * 16, wn = (wid >> 2) * 32;

    const int d  = tid >> 2;
    const int m8 = (tid & 3) << 3;
    const int w0 = m8 >> 1;

    float acc[4][4];
    #pragma unroll
    for (int j = 0; j < 4; j++)
        #pragma unroll
        for (int q = 0; q < 4; q++) acc[j][q] = 0.0f;

    float es = 0.0f;
    const int mbeg = ch * (NPIX / NCHUNK);
    const int mend = mbeg + (NPIX / NCHUNK);

    for (int m0 = mbeg; m0 < mend; m0 += 32) {
        uint4 ka = *(const uint4*)(kp + (size_t)d * NPIX + m0 + m8);
        uint4 va = *(const uint4*)(vp + (size_t)d * NPIX + m0 + m8);
        As32[d][w0 + 0] = ka.x; As32[d][w0 + 1] = ka.y;
        As32[d][w0 + 2] = ka.z; As32[d][w0 + 3] = ka.w;
        Bs32[d][w0 + 0] = va.x; Bs32[d][w0 + 1] = va.y;
        Bs32[d][w0 + 2] = va.z; Bs32[d][w0 + 3] = va.w;
        float2 f0 = __half22float2(*(__half2*)&ka.x);
        float2 f1 = __half22float2(*(__half2*)&ka.y);
        float2 f2 = __half22float2(*(__half2*)&ka.z);
        float2 f3 = __half22float2(*(__half2*)&ka.w);
        es += (f0.x + f0.y) + (f1.x + f1.y) + ((f2.x + f2.y) + (f3.x + f3.y));

        __syncthreads();

        #pragma unroll
        for (int ks = 0; ks < 2; ks++) {
            const int kk2 = ks * 8;
            uint32_t af[4], bf[4][2];
            af[0] = As32[wm + g][kk2 + t];
            af[1] = As32[wm + g + 8][kk2 + t];
            af[2] = As32[wm + g][kk2 + t + 4];
            af[3] = As32[wm + g + 8][kk2 + t + 4];
            #pragma unroll
            for (int j = 0; j < 4; j++) {
                const int c = wn + j * 8 + g;
                bf[j][0] = Bs32[c][kk2 + t];
                bf[j][1] = Bs32[c][kk2 + t + 4];
            }
            #pragma unroll
            for (int j = 0; j < 4; j++)
                mma_f16(acc[j], af, bf[j]);
        }
        __syncthreads();
    }

    float* cp = part + ((size_t)ch * 64 + bh) * PART_BH;
    const int r0 = wm + g, r1 = wm + g + 8;
    #pragma unroll
    for (int j = 0; j < 4; j++) {
        const int c = wn + j * 8 + 2 * t;
        cp[r0 * PART_LD + c]     = acc[j][0];
        cp[r0 * PART_LD + c + 1] = acc[j][1];
        cp[r1 * PART_LD + c]     = acc[j][2];
        cp[r1 * PART_LD + c + 1] = acc[j][3];
    }

    es += __shfl_xor_sync(0xffffffffu, es, 1);
    es += __shfl_xor_sync(0xffffffffu, es, 2);
    if ((tid & 3) == 0) cp[d * PART_LD + 64] = es;
}

// ---------------- reduce partials, normalize, fold Wo ----------------
__global__ void fold_kernel(const float* __restrict__ Wo, const float* __restrict__ part,
                            float* __restrict__ fold)
{
    const int bh = blockIdx.x;
    const int b = bh >> 3, h = bh & 7;

    __shared__ float cs[64][64];
    __shared__ float Sd[64];

    const int tid = threadIdx.x;
    if (tid < 64) {
        float s = 0.0f;
        #pragma unroll
        for (int ch = 0; ch < NCHUNK; ch++)
            s += part[((size_t)ch * 64 + bh) * PART_BH + tid * PART_LD + 64];
        Sd[tid] = 1.0f / s;
    }
    __syncthreads();

    for (int idx = tid; idx < 1024; idx += 256) {
        const int dd = idx >> 4, e4 = (idx & 15) * 4;
        float4 s = make_float4(0.f, 0.f, 0.f, 0.f);
        #pragma unroll
        for (int ch = 0; ch < NCHUNK; ch++) {
            float4 p = *(const float4*)(part + ((size_t)ch * 64 + bh) * PART_BH + dd * PART_LD + e4);
            s.x += p.x; s.y += p.y; s.z += p.z; s.w += p.w;
        }
        const float iv = Sd[dd];
        cs[dd][e4 + 0] = s.x * iv;
        cs[dd][e4 + 1] = s.y * iv;
        cs[dd][e4 + 2] = s.z * iv;
        cs[dd][e4 + 3] = s.w * iv;
    }
    __syncthreads();

    const int o = tid;
    float4 w[16];
    #pragma unroll
    for (int e = 0; e < 16; e++)
        w[e] = *(const float4*)(Wo + (size_t)o * HID + h * 64 + e * 4);

    float* fp = fold + ((size_t)b * NC + o) * HID + h * 64;
    for (int dd = 0; dd < 64; dd++) {
        float s = 0.0f;
        #pragma unroll
        for (int e = 0; e < 16; e++) {
            float4 c = *(const float4*)&cs[dd][e * 4];
            s += w[e].x * c.x + w[e].y * c.y + w[e].z * c.z + w[e].w * c.w;
        }
        fp[dd] = s;
    }
}

// ---------------- launch ----------------
extern "C" void kernel_launch(void* const* d_in, const int* in_sizes, int n_in,
                              void* d_out, int out_size)
{
    const float* x    = (const float*)d_in[0];
    const float* cin  = (const float*)d_in[1];
    const float* Wq   = (const float*)d_in[2];
    const float* Wk   = (const float*)d_in[3];
    const float* Wv   = (const float*)d_in[4];
    const float* Wo   = (const float*)d_in[5];
    const float* bo   = (const float*)d_in[6];
    float* out = (float*)d_out;

    __half* kvh;
    float *wkv, *pt, *fd, *cb;
    cudaGetSymbolAddress((void**)&kvh, g_kvh);
    cudaGetSymbolAddress((void**)&wkv, g_wkv);
    cudaGetSymbolAddress((void**)&pt, g_part);
    cudaGetSymbolAddress((void**)&fd, g_fold);
    cudaGetSymbolAddress((void**)&cb, g_comb);

    const float scale = 0.125f;

    pack_wkv<<<HID * NC / 256, 256>>>(Wk, Wv, wkv);

    // kv = Wkv @ cin -> half, exp on k rows  (M=1024, N=4096, K=256 per batch)
    dim3 gproj(NPIX / 128, 1024 / 128, NB);
    mma_gemm<<<gproj, 256>>>(wkv, 0, NC, cin, (long)NC * NPIX, NPIX,
                             kvh, (long)1024 * NPIX, NPIX, nullptr, NC, 1.0f, 1);

    // ctx partials
    dim3 gctx(NB * NHEAD, NCHUNK);
    ctx_partial_kernel<<<gctx, 256>>>(kvh, pt);

    // reduce + normalize + fold Wo
    fold_kernel<<<NB * NHEAD, 256>>>(Wo, pt, fd);

    // comb[b] = fold[b] @ (scale*Wq)   (M=256, N=256, K=512)
    dim3 gcomb(NC / 128, NC / 128, NB);
    mma_gemm<<<gcomb, 256>>>(fd, (long)NC * HID, HID, Wq, 0, NC,
                             cb, (long)NC * NC, NC, nullptr, HID, scale, 0);

    // out = comb @ x + bo   (M=256, N=4096, K=256)
    dim3 gfin(NPIX / 128, NC / 128, NB);
    mma_gemm<<<gfin, 256>>>(cb, (long)NC * NC, NC, x, (long)NC * NPIX, NPIX,
                            out, (long)NC * NPIX, NPIX, bo, NC, 1.0f, 0);
}